// round 8
// baseline (speedup 1.0000x reference)
#include <cuda_runtime.h>
#include <cstdint>
#include <cstdio>

#define HID 256
#define HS  512
#define NH  8
#define HD  64
#define NTOK 8
#define BB  8

// Per-batch folded query vectors: u[b][e][ch] = (sum_d qh[b,e,d]*w_kv[ch, e*128+d]) * rms_w[ch] * 0.125
__device__ float g_u[BB][NH][HID];
// Duplicated v-weights: wdup[e][ch][d] stored as (v,v) float pairs -> native packed f32x2 operand
__device__ float g_wdup[NH * HID * HD * 2];   // 1 MB

static __device__ __forceinline__ unsigned long long pk2(float lo, float hi){
  unsigned long long r; asm("mov.b64 %0, {%1,%2};" : "=l"(r) : "f"(lo), "f"(hi)); return r;
}
static __device__ __forceinline__ void upk2(unsigned long long v, float& lo, float& hi){
  asm("mov.b64 {%0,%1}, %2;" : "=f"(lo), "=f"(hi) : "l"(v));
}
static __device__ __forceinline__ unsigned long long f2fma(unsigned long long a, unsigned long long b, unsigned long long c){
  unsigned long long d; asm("fma.rn.f32x2 %0, %1, %2, %3;" : "=l"(d) : "l"(a), "l"(b), "l"(c)); return d;
}

// ---------------- setup: qh = silu(emb[q]@w1+b1)@w2+b2 ; u = (w_kv_k,e @ qh_e) * rms_w * scale
// also builds g_wdup (striped across the 8 blocks)
__global__ void setup_kernel(const int* __restrict__ q, const float* __restrict__ emb,
                             const float* __restrict__ w1, const float* __restrict__ b1,
                             const float* __restrict__ w2, const float* __restrict__ b2,
                             const float* __restrict__ w_kv, const float* __restrict__ rms_w)
{
  __shared__ float qe[HID], s1[HS], qh[HS];
  int b = blockIdx.x, t = threadIdx.x;

  // fill wdup slice: 131072 dup-pairs total, 16384 per block
  for (int i = t; i < 16384; i += blockDim.x){
    int idx = b*16384 + i;          // pair index in [0, 131072)
    int e  = idx >> 14;             // 16384 pairs per head
    int r  = idx & 16383;
    int ch = r >> 6;
    int d  = r & 63;
    float v = w_kv[(size_t)ch*1024 + e*128 + 64 + d];
    g_wdup[idx*2]   = v;
    g_wdup[idx*2+1] = v;
  }

  if (t < HID) qe[t] = emb[(size_t)q[b]*HID + t];
  __syncthreads();
  {
    float a0=0.f,a1=0.f,a2=0.f,a3=0.f;
    for (int i=0;i<HID;i+=4){
      a0 = fmaf(qe[i+0], w1[(i+0)*HS+t], a0);
      a1 = fmaf(qe[i+1], w1[(i+1)*HS+t], a1);
      a2 = fmaf(qe[i+2], w1[(i+2)*HS+t], a2);
      a3 = fmaf(qe[i+3], w1[(i+3)*HS+t], a3);
    }
    float acc = b1[t] + (a0+a1) + (a2+a3);
    s1[t] = acc / (1.f + expf(-acc));
  }
  __syncthreads();
  {
    float a0=0.f,a1=0.f,a2=0.f,a3=0.f;
    for (int i=0;i<HS;i+=4){
      a0 = fmaf(s1[i+0], w2[(i+0)*HS+t], a0);
      a1 = fmaf(s1[i+1], w2[(i+1)*HS+t], a1);
      a2 = fmaf(s1[i+2], w2[(i+2)*HS+t], a2);
      a3 = fmaf(s1[i+3], w2[(i+3)*HS+t], a3);
    }
    qh[t] = b2[t] + (a0+a1) + (a2+a3);
  }
  __syncthreads();
  for (int idx=t; idx<NH*HID; idx+=blockDim.x){
    int e = idx >> 8, ch = idx & 255;
    const float* wk = w_kv + (size_t)ch*1024 + e*128;   // k-half
    float a0=0.f,a1=0.f,a2=0.f,a3=0.f;
    for (int d=0; d<HD; d+=4){
      a0 = fmaf(qh[e*HD+d+0], wk[d+0], a0);
      a1 = fmaf(qh[e*HD+d+1], wk[d+1], a1);
      a2 = fmaf(qh[e*HD+d+2], wk[d+2], a2);
      a3 = fmaf(qh[e*HD+d+3], wk[d+3], a3);
    }
    g_u[b][e][ch] = ((a0+a1)+(a2+a3)) * rms_w[ch] * 0.125f;
  }
}

// ---------------- main fused kernel: one block per (b, hrow) row of 32 pixels
// smem (floats), 16384 total = 64KB -> 2 blocks/SM:
//  [0,256)        rms_sm
//  [256,2304)     ur_sm   [ch][e]
//  [2304,2560)    rinv_sm [n][w]
//  [2560,4608)    attn_sm [e][n][w]
//  [4608,12800)   g_sm    [e][cc][w]
//  h_sm aliases the WHOLE region [0,16384) after the chunk loop (all above dead)
__global__ __launch_bounds__(256, 2) void main_kernel(const float* __restrict__ c,
    const float* __restrict__ rms_w, const float* __restrict__ w_kv,
    const float* __restrict__ w_out, const float* __restrict__ b_out,
    float* __restrict__ out)
{
  extern __shared__ float sm[];
  float* rms_sm  = sm;
  float* ur_sm   = sm + 256;
  float* rinv_sm = sm + 2304;
  float* attn_sm = sm + 2560;
  float* g_sm    = sm + 4608;
  float* h_sm    = sm;          // alias everything (valid only after chunk loop)

  const int t  = threadIdx.x;
  const int bx = blockIdx.x;
  const int b  = bx >> 5, hrow = bx & 31;
  const int w  = t & 31;
  const int n  = t >> 5;        // warp id
  const int lane = w;

  rms_sm[t] = rms_w[t];
  {
    int ch = t;
    #pragma unroll
    for (int e=0;e<NH;e++) ur_sm[ch*NH + e] = g_u[b][e][ch];
  }
  __syncthreads();

  const float* cp = c + ((size_t)(b*NTOK + n)*HID)*1024 + hrow*32 + w;

  // ---- pass 1: stream c once (unroll-8 batched loads); rms sum + 8 head dots
  float ss = 0.f;
  unsigned long long s2[4];
  s2[0]=s2[1]=s2[2]=s2[3]=0ull;
  const unsigned long long* urp = reinterpret_cast<const unsigned long long*>(ur_sm);
  for (int c8=0; c8<32; c8++){
    float x[8];
    #pragma unroll
    for (int j=0;j<8;j++) x[j] = __ldg(cp + (size_t)(c8*8+j)*1024);
    #pragma unroll
    for (int j=0;j<8;j++){
      unsigned long long xd = pk2(x[j],x[j]);
      int ch = c8*8+j;
      ss = fmaf(x[j],x[j],ss);
      s2[0] = f2fma(xd, urp[ch*4+0], s2[0]);
      s2[1] = f2fma(xd, urp[ch*4+1], s2[1]);
      s2[2] = f2fma(xd, urp[ch*4+2], s2[2]);
      s2[3] = f2fma(xd, urp[ch*4+3], s2[3]);
    }
  }
  float rinv = rsqrtf(ss*(1.f/256.f) + 1e-6f);
  rinv_sm[n*32+w] = rinv;
  #pragma unroll
  for (int j=0;j<4;j++){
    float lo,hi; upk2(s2[j],lo,hi);
    attn_sm[(2*j  )*256 + n*32 + w] = lo*rinv;
    attn_sm[(2*j+1)*256 + n*32 + w] = hi*rinv;
  }
  __syncthreads();

  // ---- softmax over n: thread (e = n-slot, w)
  {
    int e = n;
    float d[8], m = -1e30f;
    #pragma unroll
    for (int i=0;i<8;i++){ d[i] = attn_sm[e*256 + i*32 + w]; m = fmaxf(m,d[i]); }
    float ssum = 0.f;
    #pragma unroll
    for (int i=0;i<8;i++){ d[i] = __expf(d[i]-m); ssum += d[i]; }
    float inv = 1.f/ssum;
    #pragma unroll
    for (int i=0;i<8;i++) attn_sm[e*256 + i*32 + w] = d[i]*inv;
  }
  __syncthreads();

  // rinv for all tokens at this thread's w (used by g-phase, invariant across chunks)
  float rv[8];
  #pragma unroll
  for (int nn=0;nn<8;nn++) rv[nn] = rinv_sm[nn*32+w];

  // ---- chunk loop: g-phase (direct L2 reads of c) then h-phase (register accum)
  const int e   = n;
  const int d0  = (lane & 7) * 8;
  const int wb2 = 2*(lane >> 3);            // even w-pair base: pairs {wb2+8k, wb2+8k+1}
  unsigned long long hacc[8][4];
  #pragma unroll
  for (int i=0;i<8;i++){
    #pragma unroll
    for (int k=0;k<4;k++) hacc[i][k]=0ull;
  }
  const float* cgbase = c + ((size_t)b*NTOK*HID)*1024 + hrow*32 + w;

  for (int kc=0; kc<8; kc++){
    const int ch0 = kc*32;
    // ---- g-phase: thread (ccg = warp, w) computes g for ch = ch0+ccg*4+j2, all heads
    {
      const int ccg = n;
      const int chb = ch0 + ccg*4;
      float rmsj[4];
      #pragma unroll
      for (int j2=0;j2<4;j2++) rmsj[j2] = rms_sm[chb+j2];
      float ga[8][4];
      #pragma unroll
      for (int i=0;i<8;i++){
        #pragma unroll
        for (int j2=0;j2<4;j2++) ga[i][j2]=0.f;
      }
      float cva[4], cvb[4];
      #pragma unroll
      for (int j2=0;j2<4;j2++) cva[j2] = __ldg(cgbase + (size_t)(chb + j2)*1024);
      #pragma unroll
      for (int nn=0; nn<8; nn++){
        float* cur = (nn & 1) ? cvb : cva;
        float* nxt = (nn & 1) ? cva : cvb;
        if (nn < 7){
          #pragma unroll
          for (int j2=0;j2<4;j2++) nxt[j2] = __ldg(cgbase + (size_t)((nn+1)*HID + chb + j2)*1024);
        }
        float a[8];
        #pragma unroll
        for (int ee=0;ee<8;ee++) a[ee] = attn_sm[ee*256 + nn*32 + w];
        #pragma unroll
        for (int j2=0;j2<4;j2++){
          float cn = cur[j2] * rv[nn] * rmsj[j2];
          #pragma unroll
          for (int ee=0;ee<8;ee++) ga[ee][j2] = fmaf(a[ee], cn, ga[ee][j2]);
        }
      }
      #pragma unroll
      for (int ee=0;ee<8;ee++){
        #pragma unroll
        for (int j2=0;j2<4;j2++)
          g_sm[ee*1024 + (ccg*4+j2)*32 + w] = ga[ee][j2];
      }
    }
    __syncthreads();
    // ---- h-phase: warp = head e; thread covers d0..d0+7 (scalars) x 4 w-pairs
    {
      ulonglong2 qa0,qa1,qa2,qa3, qb0,qb1,qb2,qb3;
      {
        const ulonglong2* p = reinterpret_cast<const ulonglong2*>(
            g_wdup + (((size_t)(e*HID + ch0)*HD) + d0)*2);
        qa0=__ldg(p+0); qa1=__ldg(p+1); qa2=__ldg(p+2); qa3=__ldg(p+3);
      }
      #pragma unroll 2
      for (int cc=0; cc<32; cc++){
        if (cc < 31){
          const ulonglong2* p = reinterpret_cast<const ulonglong2*>(
              g_wdup + (((size_t)(e*HID + ch0+cc+1)*HD) + d0)*2);
          if (cc & 1){ qa0=__ldg(p+0); qa1=__ldg(p+1); qa2=__ldg(p+2); qa3=__ldg(p+3); }
          else       { qb0=__ldg(p+0); qb1=__ldg(p+1); qb2=__ldg(p+2); qb3=__ldg(p+3); }
        }
        ulonglong2 w0 = (cc & 1) ? qb0 : qa0;
        ulonglong2 w1 = (cc & 1) ? qb1 : qa1;
        ulonglong2 w2 = (cc & 1) ? qb2 : qa2;
        ulonglong2 w3 = (cc & 1) ? qb3 : qa3;
        const unsigned long long* gp =
            reinterpret_cast<const unsigned long long*>(g_sm + e*1024 + cc*32 + wb2);
        #pragma unroll
        for (int k=0;k<4;k++){
          unsigned long long g2 = gp[4*k];
          hacc[0][k] = f2fma(w0.x, g2, hacc[0][k]);
          hacc[1][k] = f2fma(w0.y, g2, hacc[1][k]);
          hacc[2][k] = f2fma(w1.x, g2, hacc[2][k]);
          hacc[3][k] = f2fma(w1.y, g2, hacc[3][k]);
          hacc[4][k] = f2fma(w2.x, g2, hacc[4][k]);
          hacc[5][k] = f2fma(w2.y, g2, hacc[5][k]);
          hacc[6][k] = f2fma(w3.x, g2, hacc[6][k]);
          hacc[7][k] = f2fma(w3.y, g2, hacc[7][k]);
        }
      }
    }
    __syncthreads();   // g_sm reusable next chunk; also orders final h_sm alias write
  }

  // ---- write h to aliased smem; even swizzle sw2 = ((row>>2)<<1)&31, STS64 w-pairs
  {
    #pragma unroll
    for (int dr=0; dr<8; dr++){
      int row = e*64 + d0 + dr;
      int sw2 = ((row >> 2) << 1) & 31;
      #pragma unroll
      for (int k=0;k<4;k++){
        int col = (wb2 + 8*k + sw2) & 31;
        *reinterpret_cast<unsigned long long*>(h_sm + row*32 + col) = hacc[dr][k];
      }
    }
  }
  __syncthreads();

  // ---- epilogue: out[o][w] = sum_ed h[ed][w] * w_out[ed][o]
  // thread: 16 o (8 u64 o-pairs, LDG128) x 2 w (one LDS64); ping-pong w_out prefetch
  {
    const int o0  = n*32 + (lane >> 4)*16;
    const int wj0 = (lane & 15)*2;
    unsigned long long oacc[8][2];
    #pragma unroll
    for (int i=0;i<8;i++){ oacc[i][0]=0ull; oacc[i][1]=0ull; }

    ulonglong2 qa0,qa1,qa2,qa3, qb0,qb1,qb2,qb3;
    {
      const ulonglong2* wr = reinterpret_cast<const ulonglong2*>(w_out + o0);
      qa0=__ldg(wr+0); qa1=__ldg(wr+1); qa2=__ldg(wr+2); qa3=__ldg(wr+3);
    }
    for (int ed=0; ed<512; ed+=2){
      {
        const ulonglong2* wr = reinterpret_cast<const ulonglong2*>(w_out + (size_t)(ed+1)*256 + o0);
        qb0=__ldg(wr+0); qb1=__ldg(wr+1); qb2=__ldg(wr+2); qb3=__ldg(wr+3);
      }
      int sw2 = ((ed >> 2) << 1) & 31;          // same for ed and ed+1 (ed even)
      {
        unsigned long long hp = *reinterpret_cast<const unsigned long long*>(
            h_sm + ed*32 + ((wj0 + sw2) & 31));
        float h0,h1; upk2(hp,h0,h1);
        unsigned long long hd0 = pk2(h0,h0), hd1 = pk2(h1,h1);
        oacc[0][0]=f2fma(qa0.x,hd0,oacc[0][0]); oacc[0][1]=f2fma(qa0.x,hd1,oacc[0][1]);
        oacc[1][0]=f2fma(qa0.y,hd0,oacc[1][0]); oacc[1][1]=f2fma(qa0.y,hd1,oacc[1][1]);
        oacc[2][0]=f2fma(qa1.x,hd0,oacc[2][0]); oacc[2][1]=f2fma(qa1.x,hd1,oacc[2][1]);
        oacc[3][0]=f2fma(qa1.y,hd0,oacc[3][0]); oacc[3][1]=f2fma(qa1.y,hd1,oacc[3][1]);
        oacc[4][0]=f2fma(qa2.x,hd0,oacc[4][0]); oacc[4][1]=f2fma(qa2.x,hd1,oacc[4][1]);
        oacc[5][0]=f2fma(qa2.y,hd0,oacc[5][0]); oacc[5][1]=f2fma(qa2.y,hd1,oacc[5][1]);
        oacc[6][0]=f2fma(qa3.x,hd0,oacc[6][0]); oacc[6][1]=f2fma(qa3.x,hd1,oacc[6][1]);
        oacc[7][0]=f2fma(qa3.y,hd0,oacc[7][0]); oacc[7][1]=f2fma(qa3.y,hd1,oacc[7][1]);
      }
      if (ed+2 < 512){
        const ulonglong2* wr = reinterpret_cast<const ulonglong2*>(w_out + (size_t)(ed+2)*256 + o0);
        qa0=__ldg(wr+0); qa1=__ldg(wr+1); qa2=__ldg(wr+2); qa3=__ldg(wr+3);
      }
      {
        unsigned long long hp = *reinterpret_cast<const unsigned long long*>(
            h_sm + (ed+1)*32 + ((wj0 + sw2) & 31));
        float h0,h1; upk2(hp,h0,h1);
        unsigned long long hd0 = pk2(h0,h0), hd1 = pk2(h1,h1);
        oacc[0][0]=f2fma(qb0.x,hd0,oacc[0][0]); oacc[0][1]=f2fma(qb0.x,hd1,oacc[0][1]);
        oacc[1][0]=f2fma(qb0.y,hd0,oacc[1][0]); oacc[1][1]=f2fma(qb0.y,hd1,oacc[1][1]);
        oacc[2][0]=f2fma(qb1.x,hd0,oacc[2][0]); oacc[2][1]=f2fma(qb1.x,hd1,oacc[2][1]);
        oacc[3][0]=f2fma(qb1.y,hd0,oacc[3][0]); oacc[3][1]=f2fma(qb1.y,hd1,oacc[3][1]);
        oacc[4][0]=f2fma(qb2.x,hd0,oacc[4][0]); oacc[4][1]=f2fma(qb2.x,hd1,oacc[4][1]);
        oacc[5][0]=f2fma(qb2.y,hd0,oacc[5][0]); oacc[5][1]=f2fma(qb2.y,hd1,oacc[5][1]);
        oacc[6][0]=f2fma(qb3.x,hd0,oacc[6][0]); oacc[6][1]=f2fma(qb3.x,hd1,oacc[6][1]);
        oacc[7][0]=f2fma(qb3.y,hd0,oacc[7][0]); oacc[7][1]=f2fma(qb3.y,hd1,oacc[7][1]);
      }
    }

    float bo[16];
    {
      const float4* bp = reinterpret_cast<const float4*>(b_out + o0);
      #pragma unroll
      for (int i=0;i<4;i++){
        float4 v = __ldg(bp + i);
        bo[4*i+0]=v.x; bo[4*i+1]=v.y; bo[4*i+2]=v.z; bo[4*i+3]=v.w;
      }
    }
    const size_t pbase = (size_t)b*256*1024 + (size_t)hrow*32;
    #pragma unroll
    for (int op=0; op<8; op++){
      #pragma unroll
      for (int j=0;j<2;j++){
        float lo,hi; upk2(oacc[op][j],lo,hi);
        int oa = o0 + 2*op;
        out[pbase + (size_t)oa*1024     + wj0 + j] = lo + bo[2*op];
        out[pbase + (size_t)(oa+1)*1024 + wj0 + j] = hi + bo[2*op+1];
      }
    }
  }
}

extern "C" void kernel_launch(void* const* d_in, const int* in_sizes, int n_in,
                              void* d_out, int out_size) {
  const int*   q     = (const int*)  d_in[0];
  const float* c     = (const float*)d_in[1];
  const float* rms_w = (const float*)d_in[2];
  const float* emb   = (const float*)d_in[3];
  const float* w1    = (const float*)d_in[4];
  const float* b1    = (const float*)d_in[5];
  const float* w2    = (const float*)d_in[6];
  const float* b2    = (const float*)d_in[7];
  const float* w_kv  = (const float*)d_in[8];
  const float* w_out = (const float*)d_in[9];
  const float* b_out = (const float*)d_in[10];
  float* out = (float*)d_out;

  setup_kernel<<<8, 512>>>(q, emb, w1, b1, w2, b2, w_kv, rms_w);

  int smem_bytes = 16384 * 4;  // 64KB -> 2 blocks/SM
  cudaFuncSetAttribute(main_kernel, cudaFuncAttributeMaxDynamicSharedMemorySize, smem_bytes);
  main_kernel<<<256, 256, smem_bytes>>>(c, rms_w, w_kv, w_out, b_out, out);
}

// round 9
// speedup vs baseline: 1.2235x; 1.2235x over previous
#include <cuda_runtime.h>
#include <cstdint>
#include <cstdio>

#define HID 256
#define HS  512
#define NH  8
#define HD  64
#define NTOK 8
#define BB  8

// Per-batch folded query vectors: u[b][e][ch] = (sum_d qh[b,e,d]*w_kv[ch, e*128+d]) * rms_w[ch] * 0.125
__device__ float g_u[BB][NH][HID];
// Intermediate h, ed-major: g_h[ed][pix], pix = b*1024 + hrow*32 + w.  16.8 MB
__device__ float g_h[HS * 8192];

static __device__ __forceinline__ unsigned long long pk2(float lo, float hi){
  unsigned long long r; asm("mov.b64 %0, {%1,%2};" : "=l"(r) : "f"(lo), "f"(hi)); return r;
}
static __device__ __forceinline__ void upk2(unsigned long long v, float& lo, float& hi){
  asm("mov.b64 {%0,%1}, %2;" : "=f"(lo), "=f"(hi) : "l"(v));
}
static __device__ __forceinline__ unsigned long long f2fma(unsigned long long a, unsigned long long b, unsigned long long c){
  unsigned long long d; asm("fma.rn.f32x2 %0, %1, %2, %3;" : "=l"(d) : "l"(a), "l"(b), "l"(c)); return d;
}

// ---------------- setup: qh = silu(emb[q]@w1+b1)@w2+b2 ; u = (w_kv_k,e @ qh_e) * rms_w * scale
__global__ void setup_kernel(const int* __restrict__ q, const float* __restrict__ emb,
                             const float* __restrict__ w1, const float* __restrict__ b1,
                             const float* __restrict__ w2, const float* __restrict__ b2,
                             const float* __restrict__ w_kv, const float* __restrict__ rms_w)
{
  __shared__ float qe[HID], s1[HS], qh[HS];
  int b = blockIdx.x, t = threadIdx.x;
  if (t < HID) qe[t] = emb[(size_t)q[b]*HID + t];
  __syncthreads();
  {
    float a0=0.f,a1=0.f,a2=0.f,a3=0.f;
    for (int i=0;i<HID;i+=4){
      a0 = fmaf(qe[i+0], w1[(i+0)*HS+t], a0);
      a1 = fmaf(qe[i+1], w1[(i+1)*HS+t], a1);
      a2 = fmaf(qe[i+2], w1[(i+2)*HS+t], a2);
      a3 = fmaf(qe[i+3], w1[(i+3)*HS+t], a3);
    }
    float acc = b1[t] + (a0+a1) + (a2+a3);
    s1[t] = acc / (1.f + expf(-acc));
  }
  __syncthreads();
  {
    float a0=0.f,a1=0.f,a2=0.f,a3=0.f;
    for (int i=0;i<HS;i+=4){
      a0 = fmaf(s1[i+0], w2[(i+0)*HS+t], a0);
      a1 = fmaf(s1[i+1], w2[(i+1)*HS+t], a1);
      a2 = fmaf(s1[i+2], w2[(i+2)*HS+t], a2);
      a3 = fmaf(s1[i+3], w2[(i+3)*HS+t], a3);
    }
    qh[t] = b2[t] + (a0+a1) + (a2+a3);
  }
  __syncthreads();
  for (int idx=t; idx<NH*HID; idx+=blockDim.x){
    int e = idx >> 8, ch = idx & 255;
    const float* wk = w_kv + (size_t)ch*1024 + e*128;   // k-half
    float a0=0.f,a1=0.f,a2=0.f,a3=0.f;
    for (int d=0; d<HD; d+=4){
      a0 = fmaf(qh[e*HD+d+0], wk[d+0], a0);
      a1 = fmaf(qh[e*HD+d+1], wk[d+1], a1);
      a2 = fmaf(qh[e*HD+d+2], wk[d+2], a2);
      a3 = fmaf(qh[e*HD+d+3], wk[d+3], a3);
    }
    g_u[b][e][ch] = ((a0+a1)+(a2+a3)) * rms_w[ch] * 0.125f;
  }
}

// ---------------- kernel1: pass1 + softmax + g + h; writes h to g_h (ed-major)
// smem (floats), 18944 total = 75.8KB -> 2 blocks/SM:
//  [0,256)        rms_sm
//  [256,512)      rinv_sm [n][w]
//  [512,2560)     attn_sm [e][n][w]
//  [2560,10752)   cn_sm   [n][cc][w]   (ur_sm aliases its first 2048 during pass 1)
//  [10752,18944)  g_sm    [e][cc][w]
__global__ __launch_bounds__(256, 2) void main_kernel(const float* __restrict__ c,
    const float* __restrict__ rms_w, const float* __restrict__ w_kv)
{
  extern __shared__ float sm[];
  float* rms_sm  = sm;
  float* rinv_sm = sm + 256;
  float* attn_sm = sm + 512;
  float* cn_sm   = sm + 2560;
  float* ur_sm   = sm + 2560;   // alias (dead once chunk loop starts)
  float* g_sm    = sm + 10752;

  const int t  = threadIdx.x;
  const int bx = blockIdx.x;
  const int b  = bx >> 5, hrow = bx & 31;
  const int w  = t & 31;
  const int n  = t >> 5;        // warp id
  const int lane = w;

  rms_sm[t] = rms_w[t];
  {
    int ch = t;
    #pragma unroll
    for (int e=0;e<NH;e++) ur_sm[ch*NH + e] = g_u[b][e][ch];
  }
  __syncthreads();

  const float* cp = c + ((size_t)(b*NTOK + n)*HID)*1024 + hrow*32 + w;

  // ---- pass 1: stream c once (unroll-8 batched loads); rms sum + 8 head dots
  float ss = 0.f;
  unsigned long long s2[4];
  s2[0]=s2[1]=s2[2]=s2[3]=0ull;
  const unsigned long long* urp = reinterpret_cast<const unsigned long long*>(ur_sm);
  for (int c8=0; c8<32; c8++){
    float x[8];
    #pragma unroll
    for (int j=0;j<8;j++) x[j] = __ldg(cp + (size_t)(c8*8+j)*1024);
    #pragma unroll
    for (int j=0;j<8;j++){
      unsigned long long xd = pk2(x[j],x[j]);
      int ch = c8*8+j;
      ss = fmaf(x[j],x[j],ss);
      s2[0] = f2fma(xd, urp[ch*4+0], s2[0]);
      s2[1] = f2fma(xd, urp[ch*4+1], s2[1]);
      s2[2] = f2fma(xd, urp[ch*4+2], s2[2]);
      s2[3] = f2fma(xd, urp[ch*4+3], s2[3]);
    }
  }
  float rinv = rsqrtf(ss*(1.f/256.f) + 1e-6f);
  rinv_sm[n*32+w] = rinv;
  #pragma unroll
  for (int j=0;j<4;j++){
    float lo,hi; upk2(s2[j],lo,hi);
    attn_sm[(2*j  )*256 + n*32 + w] = lo*rinv;
    attn_sm[(2*j+1)*256 + n*32 + w] = hi*rinv;
  }
  __syncthreads();

  // ---- softmax over n: thread (e = n-slot, w)
  {
    int e = n;
    float d[8], m = -1e30f;
    #pragma unroll
    for (int i=0;i<8;i++){ d[i] = attn_sm[e*256 + i*32 + w]; m = fmaxf(m,d[i]); }
    float ssum = 0.f;
    #pragma unroll
    for (int i=0;i<8;i++){ d[i] = __expf(d[i]-m); ssum += d[i]; }
    float inv = 1.f/ssum;
    #pragma unroll
    for (int i=0;i<8;i++) attn_sm[e*256 + i*32 + w] = d[i]*inv;
  }
  __syncthreads();

  // ---- chunk loop: stage cn, compute g, accumulate h in registers
  const int e     = n;
  const int d0    = (lane & 7) * 8;
  const int wbase = lane >> 3;            // 0..3; w values wbase + 4k
  unsigned long long hacc[4][8];
  #pragma unroll
  for (int i=0;i<4;i++){
    #pragma unroll
    for (int k=0;k<8;k++) hacc[i][k]=0ull;
  }
  const ulonglong2* wvp_base =
      reinterpret_cast<const ulonglong2*>(w_kv + e*128 + 64 + d0);  // row stride 256 ull2

  for (int kc=0; kc<8; kc++){
    const int ch0 = kc*32;
    // stage normalized c chunk: thread (n, w) handles its own token
    {
      #pragma unroll 4
      for (int cc=0; cc<32; cc++){
        float x = __ldg(cp + (size_t)(ch0+cc)*1024);
        cn_sm[n*1024 + cc*32 + w] = x * rinv * rms_sm[ch0+cc];
      }
    }
    __syncthreads();
    // g[e][cc][w] = sum_n attn[e][n][w] * cn[n][cc][w]; thread (ccg=n-slot, w) does 4 cc, all e
    {
      int ccg = n;
      float ga[8][4];
      #pragma unroll
      for (int i=0;i<8;i++){
        #pragma unroll
        for (int j2=0;j2<4;j2++) ga[i][j2]=0.f;
      }
      #pragma unroll
      for (int nn=0; nn<8; nn++){
        float a[8];
        #pragma unroll
        for (int ee=0;ee<8;ee++) a[ee] = attn_sm[ee*256 + nn*32 + w];
        #pragma unroll
        for (int j2=0;j2<4;j2++){
          float cv = cn_sm[nn*1024 + (ccg*4+j2)*32 + w];
          #pragma unroll
          for (int ee=0;ee<8;ee++) ga[ee][j2] = fmaf(a[ee], cv, ga[ee][j2]);
        }
      }
      #pragma unroll
      for (int ee=0;ee<8;ee++){
        #pragma unroll
        for (int j2=0;j2<4;j2++)
          g_sm[ee*1024 + (ccg*4+j2)*32 + w] = ga[ee][j2];
      }
    }
    __syncthreads();
    // h-phase: warp = head e; weights as native packed d-pairs, g dup'd via pk
    {
      const float* gbase = g_sm + e*1024 + wbase;
      #pragma unroll 2
      for (int cc=0; cc<32; cc++){
        const int ch = ch0 + cc;
        ulonglong2 wv0 = __ldg(wvp_base + (size_t)ch*256);
        ulonglong2 wv1 = __ldg(wvp_base + (size_t)ch*256 + 1);
        const float* gp = gbase + cc*32;
        #pragma unroll
        for (int k=0;k<8;k++){
          float gv = gp[4*k];
          unsigned long long gd = pk2(gv,gv);
          hacc[0][k] = f2fma(wv0.x, gd, hacc[0][k]);
          hacc[1][k] = f2fma(wv0.y, gd, hacc[1][k]);
          hacc[2][k] = f2fma(wv1.x, gd, hacc[2][k]);
          hacc[3][k] = f2fma(wv1.y, gd, hacc[3][k]);
        }
      }
    }
    __syncthreads();
  }

  // ---- write h to global, ed-major (coalesced in 16B segments)
  {
    const int pixb = b*1024 + hrow*32 + wbase;
    #pragma unroll
    for (int dp=0; dp<4; dp++){
      int ed = e*64 + d0 + 2*dp;
      float* r0 = g_h + (size_t)ed*8192 + pixb;
      float* r1 = r0 + 8192;
      #pragma unroll
      for (int k=0;k<8;k++){
        float lo,hi; upk2(hacc[dp][k],lo,hi);
        r0[4*k] = lo;
        r1[4*k] = hi;
      }
    }
  }
}

// ---------------- kernel2: out[pix, o] = h[pix, :] @ w_out + b_out
// M=8192, N=256, K=512.  Block tile 128M x 64N, grid (64, 4), 256 threads.
// Thread tile: 4 m-pairs (m = 2*mg + 32j) x 4 n.  Software-pipelined staging.
__global__ __launch_bounds__(256) void out_gemm(const float* __restrict__ w_out,
                                                const float* __restrict__ b_out,
                                                float* __restrict__ out)
{
  __shared__ float a_sm[32*128];   // [kk][m]
  __shared__ float b_sm[32*64];    // [kk][n]
  const int t = threadIdx.x;
  const int Mbase = blockIdx.x * 128;
  const int Nbase = blockIdx.y * 64;
  const int mg = t & 15, ng = t >> 4;

  unsigned long long acc[4][4];
  #pragma unroll
  for (int j=0;j<4;j++){
    #pragma unroll
    for (int nn=0;nn<4;nn++) acc[j][nn]=0ull;
  }

  float4 ra[4], rb[2];
  // prefetch chunk 0
  #pragma unroll
  for (int i=0;i<4;i++){
    int l = i*256 + t, kk = l >> 5, mf = l & 31;
    ra[i] = __ldg(reinterpret_cast<const float4*>(g_h + (size_t)kk*8192 + Mbase + mf*4));
  }
  #pragma unroll
  for (int i=0;i<2;i++){
    int l = i*256 + t, kk = l >> 4, nf = l & 15;
    rb[i] = __ldg(reinterpret_cast<const float4*>(w_out + (size_t)kk*256 + Nbase + nf*4));
  }

  for (int kc=0; kc<16; kc++){
    #pragma unroll
    for (int i=0;i<4;i++){
      int l = i*256 + t, kk = l >> 5, mf = l & 31;
      *reinterpret_cast<float4*>(a_sm + kk*128 + mf*4) = ra[i];
    }
    #pragma unroll
    for (int i=0;i<2;i++){
      int l = i*256 + t, kk = l >> 4, nf = l & 15;
      *reinterpret_cast<float4*>(b_sm + kk*64 + nf*4) = rb[i];
    }
    __syncthreads();
    if (kc < 15){
      int k0 = (kc+1)*32;
      #pragma unroll
      for (int i=0;i<4;i++){
        int l = i*256 + t, kk = l >> 5, mf = l & 31;
        ra[i] = __ldg(reinterpret_cast<const float4*>(g_h + (size_t)(k0+kk)*8192 + Mbase + mf*4));
      }
      #pragma unroll
      for (int i=0;i<2;i++){
        int l = i*256 + t, kk = l >> 4, nf = l & 15;
        rb[i] = __ldg(reinterpret_cast<const float4*>(w_out + (size_t)(k0+kk)*256 + Nbase + nf*4));
      }
    }
    #pragma unroll 4
    for (int kk=0; kk<32; kk++){
      unsigned long long am[4];
      #pragma unroll
      for (int j=0;j<4;j++)
        am[j] = *reinterpret_cast<const unsigned long long*>(a_sm + kk*128 + 2*mg + 32*j);
      #pragma unroll
      for (int nn=0;nn<4;nn++){
        float bv = b_sm[kk*64 + ng*4 + nn];
        unsigned long long bd = pk2(bv,bv);
        #pragma unroll
        for (int j=0;j<4;j++) acc[j][nn] = f2fma(am[j], bd, acc[j][nn]);
      }
    }
    __syncthreads();
  }

  // store: out[b][o][pix_local], m-pairs are consecutive pixels -> float2 stores
  const int bb = Mbase >> 10;
  const int pl = (Mbase & 1023) + 2*mg;
  #pragma unroll
  for (int nn=0;nn<4;nn++){
    int o = Nbase + ng*4 + nn;
    float bo = __ldg(b_out + o);
    float* op = out + (size_t)bb*262144 + (size_t)o*1024 + pl;
    #pragma unroll
    for (int j=0;j<4;j++){
      float lo,hi; upk2(acc[j][nn],lo,hi);
      float2 v = make_float2(lo+bo, hi+bo);
      *reinterpret_cast<float2*>(op + 32*j) = v;
    }
  }
}

extern "C" void kernel_launch(void* const* d_in, const int* in_sizes, int n_in,
                              void* d_out, int out_size) {
  const int*   q     = (const int*)  d_in[0];
  const float* c     = (const float*)d_in[1];
  const float* rms_w = (const float*)d_in[2];
  const float* emb   = (const float*)d_in[3];
  const float* w1    = (const float*)d_in[4];
  const float* b1    = (const float*)d_in[5];
  const float* w2    = (const float*)d_in[6];
  const float* b2    = (const float*)d_in[7];
  const float* w_kv  = (const float*)d_in[8];
  const float* w_out = (const float*)d_in[9];
  const float* b_out = (const float*)d_in[10];
  float* out = (float*)d_out;

  setup_kernel<<<8, 512>>>(q, emb, w1, b1, w2, b2, w_kv, rms_w);

  int smem_bytes = 18944 * 4;  // 75.8KB -> 2 blocks/SM
  cudaFuncSetAttribute(main_kernel, cudaFuncAttributeMaxDynamicSharedMemorySize, smem_bytes);
  main_kernel<<<256, 256, smem_bytes>>>(c, rms_w, w_kv);

  out_gemm<<<dim3(64, 4), 256>>>(w_out, b_out, out);
}

// round 10
// speedup vs baseline: 1.8045x; 1.4748x over previous
#include <cuda_runtime.h>
#include <cstdint>
#include <cstdio>

#define HID 256
#define HS  512
#define NH  8
#define HD  64
#define NTOK 8
#define BB  8

// Per-batch folded query vectors: u[b][e][ch] = (sum_d qh[b,e,d]*w_kv[ch, e*128+d]) * rms_w[ch] * 0.125
__device__ float g_u[BB][NH][HID];
// MLP intermediates
__device__ float g_s1[BB][HS];
__device__ float g_qh[BB][HS];
// Intermediate h, ed-major: g_h[ed][pix], pix = b*1024 + hrow*32 + w.  16.8 MB
__device__ float g_h[HS * 8192];

static __device__ __forceinline__ unsigned long long pk2(float lo, float hi){
  unsigned long long r; asm("mov.b64 %0, {%1,%2};" : "=l"(r) : "f"(lo), "f"(hi)); return r;
}
static __device__ __forceinline__ void upk2(unsigned long long v, float& lo, float& hi){
  asm("mov.b64 {%0,%1}, %2;" : "=f"(lo), "=f"(hi) : "l"(v));
}
static __device__ __forceinline__ unsigned long long f2fma(unsigned long long a, unsigned long long b, unsigned long long c){
  unsigned long long d; asm("fma.rn.f32x2 %0, %1, %2, %3;" : "=l"(d) : "l"(a), "l"(b), "l"(c)); return d;
}

// ---------------- setup stage 1: s1 = silu(emb[q] @ w1 + b1)   grid (8 b, 8 slice), 256 thr
__global__ void setup_s1(const int* __restrict__ q, const float* __restrict__ emb,
                         const float* __restrict__ w1, const float* __restrict__ b1)
{
  __shared__ float red[4][64];
  __shared__ float qe[HID];
  const int b = blockIdx.x, slice = blockIdx.y, t = threadIdx.x;
  if (t < HID) qe[t] = __ldg(emb + (size_t)__ldg(q + b)*HID + t);
  __syncthreads();
  const int cl = t & 63, qq = t >> 6;
  const int col = slice*64 + cl;
  const float* wcol = w1 + col;
  float a0=0.f, a1=0.f;
  const int i0 = qq*64;
  #pragma unroll 8
  for (int i=0; i<64; i+=2){
    a0 = fmaf(qe[i0+i  ], __ldg(wcol + (size_t)(i0+i  )*HS), a0);
    a1 = fmaf(qe[i0+i+1], __ldg(wcol + (size_t)(i0+i+1)*HS), a1);
  }
  red[qq][cl] = a0 + a1;
  __syncthreads();
  if (t < 64){
    float s = red[0][t]+red[1][t]+red[2][t]+red[3][t] + __ldg(b1 + slice*64 + t);
    g_s1[b][slice*64+t] = s / (1.f + expf(-s));
  }
}

// ---------------- setup stage 2: qh = s1 @ w2 + b2   grid (8 b, 8 slice), 256 thr
__global__ void setup_qh(const float* __restrict__ w2, const float* __restrict__ b2)
{
  __shared__ float red[4][64];
  __shared__ float s1s[HS];
  const int b = blockIdx.x, slice = blockIdx.y, t = threadIdx.x;
  s1s[t]     = g_s1[b][t];
  s1s[t+256] = g_s1[b][t+256];
  __syncthreads();
  const int cl = t & 63, qq = t >> 6;
  const int col = slice*64 + cl;
  const float* wcol = w2 + col;
  float a0=0.f, a1=0.f;
  const int i0 = qq*128;
  #pragma unroll 8
  for (int i=0; i<128; i+=2){
    a0 = fmaf(s1s[i0+i  ], __ldg(wcol + (size_t)(i0+i  )*HS), a0);
    a1 = fmaf(s1s[i0+i+1], __ldg(wcol + (size_t)(i0+i+1)*HS), a1);
  }
  red[qq][cl] = a0 + a1;
  __syncthreads();
  if (t < 64)
    g_qh[b][slice*64+t] = red[0][t]+red[1][t]+red[2][t]+red[3][t] + __ldg(b2 + slice*64 + t);
}

// ---------------- setup stage 3: u[b][e][ch] = (w_kv_k[ch,e,:] . qh[b,e,:]) * rms_w[ch]/8
// grid (8 b, 8 e), 256 thr (one per ch)
__global__ void setup_u(const float* __restrict__ w_kv, const float* __restrict__ rms_w)
{
  __shared__ float qh_sm[64];
  const int b = blockIdx.x, e = blockIdx.y, t = threadIdx.x;
  if (t < 64) qh_sm[t] = g_qh[b][e*64 + t];
  __syncthreads();
  const float4* wk = reinterpret_cast<const float4*>(w_kv + (size_t)t*1024 + e*128);
  float a0=0.f, a1=0.f;
  #pragma unroll
  for (int j=0; j<16; j+=2){
    float4 v0 = __ldg(wk + j);
    float4 v1 = __ldg(wk + j + 1);
    a0 = fmaf(qh_sm[4*j+0], v0.x, a0);
    a0 = fmaf(qh_sm[4*j+1], v0.y, a0);
    a0 = fmaf(qh_sm[4*j+2], v0.z, a0);
    a0 = fmaf(qh_sm[4*j+3], v0.w, a0);
    a1 = fmaf(qh_sm[4*j+4], v1.x, a1);
    a1 = fmaf(qh_sm[4*j+5], v1.y, a1);
    a1 = fmaf(qh_sm[4*j+6], v1.z, a1);
    a1 = fmaf(qh_sm[4*j+7], v1.w, a1);
  }
  g_u[b][e][t] = (a0+a1) * __ldg(rms_w + t) * 0.125f;
}

// ---------------- kernel1: pass1 + softmax + g + h; writes h to g_h (ed-major)
// smem (floats), 18944 total = 75.8KB -> 2 blocks/SM:
//  [0,256)        rms_sm
//  [256,512)      rinv_sm [n][w]
//  [512,2560)     attn_sm [e][n][w]
//  [2560,10752)   cn_sm   [n][cc][w]   (ur_sm aliases its first 2048 during pass 1)
//  [10752,18944)  g_sm    [e][cc][w]
__global__ __launch_bounds__(256, 2) void main_kernel(const float* __restrict__ c,
    const float* __restrict__ rms_w, const float* __restrict__ w_kv)
{
  extern __shared__ float sm[];
  float* rms_sm  = sm;
  float* rinv_sm = sm + 256;
  float* attn_sm = sm + 512;
  float* cn_sm   = sm + 2560;
  float* ur_sm   = sm + 2560;   // alias (dead once chunk loop starts)
  float* g_sm    = sm + 10752;

  const int t  = threadIdx.x;
  const int bx = blockIdx.x;
  const int b  = bx >> 5, hrow = bx & 31;
  const int w  = t & 31;
  const int n  = t >> 5;        // warp id
  const int lane = w;

  rms_sm[t] = rms_w[t];
  {
    int ch = t;
    #pragma unroll
    for (int e=0;e<NH;e++) ur_sm[ch*NH + e] = g_u[b][e][ch];
  }
  __syncthreads();

  const float* cp = c + ((size_t)(b*NTOK + n)*HID)*1024 + hrow*32 + w;

  // ---- pass 1: stream c once (unroll-8 batched loads); rms sum + 8 head dots
  float ss = 0.f;
  unsigned long long s2[4];
  s2[0]=s2[1]=s2[2]=s2[3]=0ull;
  const unsigned long long* urp = reinterpret_cast<const unsigned long long*>(ur_sm);
  for (int c8=0; c8<32; c8++){
    float x[8];
    #pragma unroll
    for (int j=0;j<8;j++) x[j] = __ldg(cp + (size_t)(c8*8+j)*1024);
    #pragma unroll
    for (int j=0;j<8;j++){
      unsigned long long xd = pk2(x[j],x[j]);
      int ch = c8*8+j;
      ss = fmaf(x[j],x[j],ss);
      s2[0] = f2fma(xd, urp[ch*4+0], s2[0]);
      s2[1] = f2fma(xd, urp[ch*4+1], s2[1]);
      s2[2] = f2fma(xd, urp[ch*4+2], s2[2]);
      s2[3] = f2fma(xd, urp[ch*4+3], s2[3]);
    }
  }
  float rinv = rsqrtf(ss*(1.f/256.f) + 1e-6f);
  rinv_sm[n*32+w] = rinv;
  #pragma unroll
  for (int j=0;j<4;j++){
    float lo,hi; upk2(s2[j],lo,hi);
    attn_sm[(2*j  )*256 + n*32 + w] = lo*rinv;
    attn_sm[(2*j+1)*256 + n*32 + w] = hi*rinv;
  }
  __syncthreads();

  // ---- softmax over n: thread (e = n-slot, w)
  {
    int e = n;
    float d[8], m = -1e30f;
    #pragma unroll
    for (int i=0;i<8;i++){ d[i] = attn_sm[e*256 + i*32 + w]; m = fmaxf(m,d[i]); }
    float ssum = 0.f;
    #pragma unroll
    for (int i=0;i<8;i++){ d[i] = __expf(d[i]-m); ssum += d[i]; }
    float inv = 1.f/ssum;
    #pragma unroll
    for (int i=0;i<8;i++) attn_sm[e*256 + i*32 + w] = d[i]*inv;
  }
  __syncthreads();

  // ---- chunk loop: stage cn, compute g, accumulate h in registers
  const int e     = n;
  const int d0    = (lane & 7) * 8;
  const int wbase = lane >> 3;            // 0..3; w values wbase + 4k
  unsigned long long hacc[4][8];
  #pragma unroll
  for (int i=0;i<4;i++){
    #pragma unroll
    for (int k=0;k<8;k++) hacc[i][k]=0ull;
  }
  const ulonglong2* wvp_base =
      reinterpret_cast<const ulonglong2*>(w_kv + e*128 + 64 + d0);  // row stride 256 ull2

  for (int kc=0; kc<8; kc++){
    const int ch0 = kc*32;
    // stage normalized c chunk: thread (n, w) handles its own token
    {
      #pragma unroll 4
      for (int cc=0; cc<32; cc++){
        float x = __ldg(cp + (size_t)(ch0+cc)*1024);
        cn_sm[n*1024 + cc*32 + w] = x * rinv * rms_sm[ch0+cc];
      }
    }
    __syncthreads();
    // g[e][cc][w] = sum_n attn[e][n][w] * cn[n][cc][w]; thread (ccg=n-slot, w) does 4 cc, all e
    {
      int ccg = n;
      float ga[8][4];
      #pragma unroll
      for (int i=0;i<8;i++){
        #pragma unroll
        for (int j2=0;j2<4;j2++) ga[i][j2]=0.f;
      }
      #pragma unroll
      for (int nn=0; nn<8; nn++){
        float a[8];
        #pragma unroll
        for (int ee=0;ee<8;ee++) a[ee] = attn_sm[ee*256 + nn*32 + w];
        #pragma unroll
        for (int j2=0;j2<4;j2++){
          float cv = cn_sm[nn*1024 + (ccg*4+j2)*32 + w];
          #pragma unroll
          for (int ee=0;ee<8;ee++) ga[ee][j2] = fmaf(a[ee], cv, ga[ee][j2]);
        }
      }
      #pragma unroll
      for (int ee=0;ee<8;ee++){
        #pragma unroll
        for (int j2=0;j2<4;j2++)
          g_sm[ee*1024 + (ccg*4+j2)*32 + w] = ga[ee][j2];
      }
    }
    __syncthreads();
    // h-phase: warp = head e; weights as native packed d-pairs, g dup'd via pk
    {
      const float* gbase = g_sm + e*1024 + wbase;
      #pragma unroll 2
      for (int cc=0; cc<32; cc++){
        const int ch = ch0 + cc;
        ulonglong2 wv0 = __ldg(wvp_base + (size_t)ch*256);
        ulonglong2 wv1 = __ldg(wvp_base + (size_t)ch*256 + 1);
        const float* gp = gbase + cc*32;
        #pragma unroll
        for (int k=0;k<8;k++){
          float gv = gp[4*k];
          unsigned long long gd = pk2(gv,gv);
          hacc[0][k] = f2fma(wv0.x, gd, hacc[0][k]);
          hacc[1][k] = f2fma(wv0.y, gd, hacc[1][k]);
          hacc[2][k] = f2fma(wv1.x, gd, hacc[2][k]);
          hacc[3][k] = f2fma(wv1.y, gd, hacc[3][k]);
        }
      }
    }
    __syncthreads();
  }

  // ---- write h to global, ed-major (coalesced in 16B segments)
  {
    const int pixb = b*1024 + hrow*32 + wbase;
    #pragma unroll
    for (int dp=0; dp<4; dp++){
      int ed = e*64 + d0 + 2*dp;
      float* r0 = g_h + (size_t)ed*8192 + pixb;
      float* r1 = r0 + 8192;
      #pragma unroll
      for (int k=0;k<8;k++){
        float lo,hi; upk2(hacc[dp][k],lo,hi);
        r0[4*k] = lo;
        r1[4*k] = hi;
      }
    }
  }
}

// ---------------- kernel2: out[pix, o] = h[pix, :] @ w_out + b_out
// M=8192, N=256, K=512.  Block tile 128M x 64N, grid (64, 4), 256 threads.
// Thread tile: 4 m-pairs (m = 2*mg + 32j) x 4 n.  Software-pipelined staging.
__global__ __launch_bounds__(256) void out_gemm(const float* __restrict__ w_out,
                                                const float* __restrict__ b_out,
                                                float* __restrict__ out)
{
  __shared__ float a_sm[32*128];   // [kk][m]
  __shared__ float b_sm[32*64];    // [kk][n]
  const int t = threadIdx.x;
  const int Mbase = blockIdx.x * 128;
  const int Nbase = blockIdx.y * 64;
  const int mg = t & 15, ng = t >> 4;

  unsigned long long acc[4][4];
  #pragma unroll
  for (int j=0;j<4;j++){
    #pragma unroll
    for (int nn=0;nn<4;nn++) acc[j][nn]=0ull;
  }

  float4 ra[4], rb[2];
  // prefetch chunk 0
  #pragma unroll
  for (int i=0;i<4;i++){
    int l = i*256 + t, kk = l >> 5, mf = l & 31;
    ra[i] = __ldg(reinterpret_cast<const float4*>(g_h + (size_t)kk*8192 + Mbase + mf*4));
  }
  #pragma unroll
  for (int i=0;i<2;i++){
    int l = i*256 + t, kk = l >> 4, nf = l & 15;
    rb[i] = __ldg(reinterpret_cast<const float4*>(w_out + (size_t)kk*256 + Nbase + nf*4));
  }

  for (int kc=0; kc<16; kc++){
    #pragma unroll
    for (int i=0;i<4;i++){
      int l = i*256 + t, kk = l >> 5, mf = l & 31;
      *reinterpret_cast<float4*>(a_sm + kk*128 + mf*4) = ra[i];
    }
    #pragma unroll
    for (int i=0;i<2;i++){
      int l = i*256 + t, kk = l >> 4, nf = l & 15;
      *reinterpret_cast<float4*>(b_sm + kk*64 + nf*4) = rb[i];
    }
    __syncthreads();
    if (kc < 15){
      int k0 = (kc+1)*32;
      #pragma unroll
      for (int i=0;i<4;i++){
        int l = i*256 + t, kk = l >> 5, mf = l & 31;
        ra[i] = __ldg(reinterpret_cast<const float4*>(g_h + (size_t)(k0+kk)*8192 + Mbase + mf*4));
      }
      #pragma unroll
      for (int i=0;i<2;i++){
        int l = i*256 + t, kk = l >> 4, nf = l & 15;
        rb[i] = __ldg(reinterpret_cast<const float4*>(w_out + (size_t)(k0+kk)*256 + Nbase + nf*4));
      }
    }
    #pragma unroll 4
    for (int kk=0; kk<32; kk++){
      unsigned long long am[4];
      #pragma unroll
      for (int j=0;j<4;j++)
        am[j] = *reinterpret_cast<const unsigned long long*>(a_sm + kk*128 + 2*mg + 32*j);
      #pragma unroll
      for (int nn=0;nn<4;nn++){
        float bv = b_sm[kk*64 + ng*4 + nn];
        unsigned long long bd = pk2(bv,bv);
        #pragma unroll
        for (int j=0;j<4;j++) acc[j][nn] = f2fma(am[j], bd, acc[j][nn]);
      }
    }
    __syncthreads();
  }

  // store: out[b][o][pix_local], m-pairs are consecutive pixels -> float2 stores
  const int bb = Mbase >> 10;
  const int pl = (Mbase & 1023) + 2*mg;
  #pragma unroll
  for (int nn=0;nn<4;nn++){
    int o = Nbase + ng*4 + nn;
    float bo = __ldg(b_out + o);
    float* op = out + (size_t)bb*262144 + (size_t)o*1024 + pl;
    #pragma unroll
    for (int j=0;j<4;j++){
      float lo,hi; upk2(acc[j][nn],lo,hi);
      float2 v = make_float2(lo+bo, hi+bo);
      *reinterpret_cast<float2*>(op + 32*j) = v;
    }
  }
}

extern "C" void kernel_launch(void* const* d_in, const int* in_sizes, int n_in,
                              void* d_out, int out_size) {
  const int*   q     = (const int*)  d_in[0];
  const float* c     = (const float*)d_in[1];
  const float* rms_w = (const float*)d_in[2];
  const float* emb   = (const float*)d_in[3];
  const float* w1    = (const float*)d_in[4];
  const float* b1    = (const float*)d_in[5];
  const float* w2    = (const float*)d_in[6];
  const float* b2    = (const float*)d_in[7];
  const float* w_kv  = (const float*)d_in[8];
  const float* w_out = (const float*)d_in[9];
  const float* b_out = (const float*)d_in[10];
  float* out = (float*)d_out;

  setup_s1<<<dim3(BB, 8), 256>>>(q, emb, w1, b1);
  setup_qh<<<dim3(BB, 8), 256>>>(w2, b2);
  setup_u <<<dim3(BB, NH), 256>>>(w_kv, rms_w);

  int smem_bytes = 18944 * 4;  // 75.8KB -> 2 blocks/SM
  cudaFuncSetAttribute(main_kernel, cudaFuncAttributeMaxDynamicSharedMemorySize, smem_bytes);
  main_kernel<<<256, 256, smem_bytes>>>(c, rms_w, w_kv);

  out_gemm<<<dim3(64, 4), 256>>>(w_out, b_out, out);
}